// round 16
// baseline (speedup 1.0000x reference)
#include <cuda_runtime.h>
#include <cstdint>

#define HH 512
#define WW 512
#define TPB 128           // 4 warps per block; each WARP owns full 512-col rows
#define NBLK 608          // 152 SMs * 4 blocks/SM (one wave at the reg-limited cap)
#define EPS 1e-6f

// scratch for per-block partial sums + completion ticket (no cudaMalloc allowed)
__device__ float g_partials[NBLK];
__device__ unsigned int g_ticket;   // zero-init; last block resets it to 0

__device__ __forceinline__ float4 ld4(const float* __restrict__ p) {
    return *reinterpret_cast<const float4*>(p);
}

// single-MUFU approximate sqrt (max rel err ~1e-7, far below 1e-3 tolerance)
__device__ __forceinline__ float fsqrt_ap(float x) {
    float r;
    asm("sqrt.approx.f32 %0, %1;" : "=f"(r) : "f"(x));
    return r;
}

// L1 prefetch: no destination register, no scoreboard — pure hint
__device__ __forceinline__ void pf_l1(const float* p) {
    asm volatile("prefetch.global.L1 [%0];" :: "l"(p));
}

// packed f32x2 helpers (FFMA2 — sm_10x; reachable only via PTX fma.rn.f32x2)
__device__ __forceinline__ uint64_t pk2(float lo, float hi) {
    uint64_t r; asm("mov.b64 %0, {%1, %2};" : "=l"(r) : "f"(lo), "f"(hi)); return r;
}
__device__ __forceinline__ void upk2(float& lo, float& hi, uint64_t v) {
    asm("mov.b64 {%0, %1}, %2;" : "=f"(lo), "=f"(hi) : "l"(v));
}
__device__ __forceinline__ uint64_t fma2_(uint64_t a, uint64_t b, uint64_t c) {
    uint64_t r; asm("fma.rn.f32x2 %0, %1, %2, %3;" : "=l"(r) : "l"(a), "l"(b), "l"(c));
    return r;
}

__global__ __launch_bounds__(TPB, 4)   // up to 128 regs; 4 blocks/SM
void grad_loss_kernel(const float* __restrict__ in, const float* __restrict__ tg,
                      float* __restrict__ out, int total_rows, float inv_n) {
    const int t     = threadIdx.x;
    const int lane  = t & 31;
    const int wid   = t >> 5;
    const int gw    = blockIdx.x * 4 + wid;       // global warp id
    const int laneL = (lane + 31) & 31;
    const int laneR = (lane + 1) & 31;

    // contiguous row slice per warp over the flattened row space
    const int nw   = NBLK * 4;
    const int base = total_rows / nw;
    const int rem  = total_rows % nw;
    const int ws   = gw * base + min(gw, rem);
    const int we   = ws + base + (gw < rem ? 1 : 0);

    const float* pi = in + (size_t)ws * WW + lane * 4;
    const float* pt = tg + (size_t)ws * WW + lane * 4;

    const float4 z4 = make_float4(0.f, 0.f, 0.f, 0.f);
    const uint64_t NEG1 = pk2(-1.f, -1.f);
    const uint64_t EPS2 = pk2(EPS, EPS);
    float sum0 = 0.f, sum1 = 0.f, sum2 = 0.f, sum3 = 0.f;

    // 3 rotating row buffers per array, 4 chunks each: roles (u, c, n)
    float4 Xi[4], Yi[4], Zi[4], Xt[4], Yt[4], Zt[4];

    #pragma unroll
    for (int k = 0; k < 4; ++k) {
        Xi[k] = (ws > 0) ? ld4(pi - WW + k * 128) : z4;   // row ws-1
        Xt[k] = (ws > 0) ? ld4(pt - WW + k * 128) : z4;
        Yi[k] = ld4(pi + k * 128);                        // row ws
        Yt[k] = ld4(pt + k * 128);
    }

    // packed-math core for one row (given u,c,n resident)
    auto rowcore = [&](const float4 (&u_i)[4], const float4 (&c_i)[4], const float4 (&n_i)[4],
                       const float4 (&u_t)[4], const float4 (&c_t)[4], const float4 (&n_t)[4]) {
        #pragma unroll
        for (int k = 0; k < 4; ++k) {
            float xl_i = (lane == 31) ? (k > 0 ? c_i[k - 1].w : 0.f) : c_i[k].w;
            float xl_t = (lane == 31) ? (k > 0 ? c_t[k - 1].w : 0.f) : c_t[k].w;
            const float lci = __shfl_sync(0xffffffffu, xl_i, laneL);
            const float lct = __shfl_sync(0xffffffffu, xl_t, laneL);
            float xr_i = (lane == 0) ? (k < 3 ? c_i[k + 1].x : 0.f) : c_i[k].x;
            float xr_t = (lane == 0) ? (k < 3 ? c_t[k + 1].x : 0.f) : c_t[k].x;
            const float rci = __shfl_sync(0xffffffffu, xr_i, laneR);
            const float rct = __shfl_sync(0xffffffffu, xr_t, laneR);

            // gv = n - u, 2-wide (xy / zw halves are aligned reg pairs -> packs elide)
            const uint64_t gva_i = fma2_(pk2(u_i[k].x, u_i[k].y), NEG1, pk2(n_i[k].x, n_i[k].y));
            const uint64_t gvb_i = fma2_(pk2(u_i[k].z, u_i[k].w), NEG1, pk2(n_i[k].z, n_i[k].w));
            const uint64_t gva_t = fma2_(pk2(u_t[k].x, u_t[k].y), NEG1, pk2(n_t[k].x, n_t[k].y));
            const uint64_t gvb_t = fma2_(pk2(u_t[k].z, u_t[k].w), NEG1, pk2(n_t[k].z, n_t[k].w));

            const float ghx_i = c_i[k].y - lci,      ghy_i = c_i[k].z - c_i[k].x;
            const float ghz_i = c_i[k].w - c_i[k].y, ghw_i = rci - c_i[k].z;
            const float ghx_t = c_t[k].y - lct,      ghy_t = c_t[k].z - c_t[k].x;
            const float ghz_t = c_t[k].w - c_t[k].y, ghw_t = rct - c_t[k].z;

            const uint64_t gha_i = pk2(ghx_i, ghy_i), ghb_i = pk2(ghz_i, ghw_i);
            const uint64_t gha_t = pk2(ghx_t, ghy_t), ghb_t = pk2(ghz_t, ghw_t);

            // q = gv^2 + gh^2 + eps, 2-wide
            const uint64_t qa_i = fma2_(gva_i, gva_i, fma2_(gha_i, gha_i, EPS2));
            const uint64_t qb_i = fma2_(gvb_i, gvb_i, fma2_(ghb_i, ghb_i, EPS2));
            const uint64_t qa_t = fma2_(gva_t, gva_t, fma2_(gha_t, gha_t, EPS2));
            const uint64_t qb_t = fma2_(gvb_t, gvb_t, fma2_(ghb_t, ghb_t, EPS2));

            float q0, q1, q2, q3, p0, p1, p2, p3;
            upk2(q0, q1, qa_i); upk2(q2, q3, qb_i);
            upk2(p0, p1, qa_t); upk2(p2, p3, qb_t);

            sum0 += fabsf(fsqrt_ap(q0) - fsqrt_ap(p0));
            sum1 += fabsf(fsqrt_ap(q1) - fsqrt_ap(p1));
            sum2 += fabsf(fsqrt_ap(q2) - fsqrt_ap(p2));
            sum3 += fabsf(fsqrt_ap(q3) - fsqrt_ap(p3));
        }
    };

    // FAST step: interior rows only (no plane-edge logic at all)
    auto fstep = [&](float4 (&u_i)[4], float4 (&c_i)[4], float4 (&n_i)[4],
                     float4 (&u_t)[4], float4 (&c_t)[4], float4 (&n_t)[4], int rg) {
        #pragma unroll
        for (int k = 0; k < 4; ++k) {
            n_i[k] = ld4(pi + WW + k * 128);
            n_t[k] = ld4(pt + WW + k * 128);
        }
        if (rg + 2 < total_rows) {
            #pragma unroll
            for (int k = 0; k < 4; ++k) {
                pf_l1(pi + 2 * WW + k * 128);
                pf_l1(pt + 2 * WW + k * 128);
            }
        }
        rowcore(u_i, c_i, n_i, u_t, c_t, n_t);
        pi += WW; pt += WW;
    };

    // GENERAL step: full plane-edge handling (rare slices)
    auto gstep = [&](float4 (&u_i)[4], float4 (&c_i)[4], float4 (&n_i)[4],
                     float4 (&u_t)[4], float4 (&c_t)[4], float4 (&n_t)[4], int rg) {
        const int r = rg & (HH - 1);
        if (r != HH - 1) {
            #pragma unroll
            for (int k = 0; k < 4; ++k) {
                n_i[k] = ld4(pi + WW + k * 128);
                n_t[k] = ld4(pt + WW + k * 128);
            }
        } else {
            #pragma unroll
            for (int k = 0; k < 4; ++k) { n_i[k] = z4; n_t[k] = z4; }
        }
        if (r == 0) {
            #pragma unroll
            for (int k = 0; k < 4; ++k) { u_i[k] = z4; u_t[k] = z4; }
        }
        if (rg + 2 < total_rows) {
            #pragma unroll
            for (int k = 0; k < 4; ++k) {
                pf_l1(pi + 2 * WW + k * 128);
                pf_l1(pt + 2 * WW + k * 128);
            }
        }
        rowcore(u_i, c_i, n_i, u_t, c_t, n_t);
        // plane-last zeroed n; next iteration needs c = real row rg+1 (rare reload)
        if (r == HH - 1 && rg + 1 < total_rows) {
            #pragma unroll
            for (int k = 0; k < 4; ++k) {
                n_i[k] = ld4(pi + WW + k * 128);
                n_t[k] = ld4(pt + WW + k * 128);
            }
        }
        pi += WW; pt += WW;
    };

    // clean slice: entirely inside one plane, no r==0 entry, no r==511 row
    const bool clean = ((ws & (HH - 1)) != 0) &&
                       (((we - 1) & (HH - 1)) != HH - 1) &&
                       ((ws >> 9) == ((we - 1) >> 9));

    int rg = ws;
    if (clean) {
        for (; rg + 3 <= we; rg += 3) {
            fstep(Xi, Yi, Zi, Xt, Yt, Zt, rg);
            fstep(Yi, Zi, Xi, Yt, Zt, Xt, rg + 1);
            fstep(Zi, Xi, Yi, Zt, Xt, Yt, rg + 2);
        }
        if (rg < we) { fstep(Xi, Yi, Zi, Xt, Yt, Zt, rg); ++rg; }
        if (rg < we) { fstep(Yi, Zi, Xi, Yt, Zt, Xt, rg); ++rg; }
    } else {
        for (; rg + 3 <= we; rg += 3) {
            gstep(Xi, Yi, Zi, Xt, Yt, Zt, rg);
            gstep(Yi, Zi, Xi, Yt, Zt, Xt, rg + 1);
            gstep(Zi, Xi, Yi, Zt, Xt, Yt, rg + 2);
        }
        if (rg < we) { gstep(Xi, Yi, Zi, Xt, Yt, Zt, rg); ++rg; }
        if (rg < we) { gstep(Yi, Zi, Xi, Yt, Zt, Xt, rg); ++rg; }
    }

    float sum = (sum0 + sum1) + (sum2 + sum3);

    // ---------- block reduction + last-block-ticket finisher ----------
    #pragma unroll
    for (int o = 16; o > 0; o >>= 1)
        sum += __shfl_down_sync(0xffffffffu, sum, o);

    __shared__ float wsum[TPB / 32];
    __shared__ bool is_last;
    if (lane == 0) wsum[wid] = sum;
    __syncthreads();

    if (t == 0) {
        float s = wsum[0] + wsum[1] + wsum[2] + wsum[3];
        g_partials[blockIdx.x] = s;
        __threadfence();                               // partial visible before ticket
        unsigned done = atomicAdd(&g_ticket, 1u);
        is_last = (done == (unsigned)(NBLK - 1));
    }
    __syncthreads();

    if (is_last) {
        const volatile float* vp = (const volatile float*)g_partials;
        float s = 0.f;
        for (int i = t; i < NBLK; i += TPB)
            s += vp[i];

        #pragma unroll
        for (int o = 16; o > 0; o >>= 1)
            s += __shfl_down_sync(0xffffffffu, s, o);

        if (lane == 0) wsum[wid] = s;
        __syncthreads();
        if (t == 0) {
            out[0] = (wsum[0] + wsum[1] + wsum[2] + wsum[3]) * inv_n;
            g_ticket = 0;                              // reset for next graph replay
        }
    }
}

extern "C" void kernel_launch(void* const* d_in, const int* in_sizes, int n_in,
                              void* d_out, int out_size) {
    const float* in = (const float*)d_in[0];
    const float* tg = (const float*)d_in[1];
    float* out = (float*)d_out;

    const int total = in_sizes[0];                 // 32*3*512*512
    const int total_rows = total / WW;             // 49152

    grad_loss_kernel<<<NBLK, TPB>>>(in, tg, out, total_rows, 1.0f / (float)total);
}

// round 17
// speedup vs baseline: 1.1548x; 1.1548x over previous
#include <cuda_runtime.h>

#define HH 512
#define WW 512
#define TPB 128           // 4 warps per block; each WARP owns full 512-col rows
#define NBLK 608          // 152 SMs * 4 blocks/SM (one wave at the reg-limited cap)
#define EPS 1e-6f

// scratch for per-block partial sums + completion ticket (no cudaMalloc allowed)
__device__ float g_partials[NBLK];
__device__ unsigned int g_ticket;   // zero-init; last block resets it to 0

__device__ __forceinline__ float4 ld4(const float* __restrict__ p) {
    return *reinterpret_cast<const float4*>(p);
}

// single-MUFU approximate sqrt (max rel err ~1e-7, far below 1e-3 tolerance)
__device__ __forceinline__ float fsqrt_ap(float x) {
    float r;
    asm("sqrt.approx.f32 %0, %1;" : "=f"(r) : "f"(x));
    return r;
}

// L1 prefetch: no destination register, no scoreboard — pure hint
__device__ __forceinline__ void pf_l1(const float* p) {
    asm volatile("prefetch.global.L1 [%0];" :: "l"(p));
}

__global__ __launch_bounds__(TPB, 4)   // up to 128 regs; 4 blocks/SM
void grad_loss_kernel(const float* __restrict__ in, const float* __restrict__ tg,
                      float* __restrict__ out, int total_rows, float inv_n) {
    const int t     = threadIdx.x;
    const int lane  = t & 31;
    const int wid   = t >> 5;
    const int gw    = blockIdx.x * 4 + wid;       // global warp id
    const int laneL = (lane + 31) & 31;           // rotate: lane reads lane-1 (wrap)
    const int laneR = (lane + 1) & 31;            // rotate: lane reads lane+1 (wrap)

    // contiguous row slice per warp over the flattened row space
    const int nw   = NBLK * 4;
    const int base = total_rows / nw;
    const int rem  = total_rows % nw;
    const int ws   = gw * base + min(gw, rem);
    const int we   = ws + base + (gw < rem ? 1 : 0);

    // lane covers cols {k*128 + lane*4 .. +4}, k=0..3 (512B coalesced chunk loads)
    const float* pi = in + (size_t)ws * WW + lane * 4;
    const float* pt = tg + (size_t)ws * WW + lane * 4;

    // SINGLE-INSTRUCTION row prefetch: one 128B line per lane.
    // lanes 0..15 cover the 16 lines of in's row, lanes 16..31 cover tg's row.
    const float* pfp = ((lane < 16) ? in : tg)
                     + (size_t)(ws + 2) * WW + (lane & 15) * 32;

    const float4 z4 = make_float4(0.f, 0.f, 0.f, 0.f);
    // 4 accumulators: break the serial FADD dependency chain
    float sum0 = 0.f, sum1 = 0.f, sum2 = 0.f, sum3 = 0.f;

    // 3 rotating row buffers per array, 4 chunks each: roles (u, c, n)
    float4 Xi[4], Yi[4], Zi[4], Xt[4], Yt[4], Zt[4];

    #pragma unroll
    for (int k = 0; k < 4; ++k) {
        Xi[k] = (ws > 0) ? ld4(pi - WW + k * 128) : z4;   // row ws-1
        Xt[k] = (ws > 0) ? ld4(pt - WW + k * 128) : z4;
        Yi[k] = ld4(pi + k * 128);                        // row ws
        Yt[k] = ld4(pt + k * 128);
    }

    // one step: 1-instr L1-prefetch of row rg+2 (both arrays), compute row rg
    auto step = [&](float4 (&u_i)[4], float4 (&c_i)[4], float4 (&n_i)[4],
                    float4 (&u_t)[4], float4 (&c_t)[4], float4 (&n_t)[4], int rg) {
        const int r = rg & (HH - 1);
        if (r != HH - 1) {                    // common path: load next row (L1 hit)
            #pragma unroll
            for (int k = 0; k < 4; ++k) {
                n_i[k] = ld4(pi + WW + k * 128);
                n_t[k] = ld4(pt + WW + k * 128);
            }
        } else {                              // plane-last row: zero-pad below
            #pragma unroll
            for (int k = 0; k < 4; ++k) { n_i[k] = z4; n_t[k] = z4; }
        }
        if (r == 0) {                         // plane-first row: zero-pad above
            #pragma unroll
            for (int k = 0; k < 4; ++k) { u_i[k] = z4; u_t[k] = z4; }
        }

        // prefetch row rg+2 of BOTH arrays with ONE instruction
        if (rg + 2 < total_rows)
            pf_l1(pfp);

        #pragma unroll
        for (int k = 0; k < 4; ++k) {
            // horizontal neighbors: rotate-shuffles, register-sourced, no loads
            float xl_i = (lane == 31) ? (k > 0 ? c_i[k - 1].w : 0.f) : c_i[k].w;
            float xl_t = (lane == 31) ? (k > 0 ? c_t[k - 1].w : 0.f) : c_t[k].w;
            const float lci = __shfl_sync(0xffffffffu, xl_i, laneL);
            const float lct = __shfl_sync(0xffffffffu, xl_t, laneL);
            float xr_i = (lane == 0) ? (k < 3 ? c_i[k + 1].x : 0.f) : c_i[k].x;
            float xr_t = (lane == 0) ? (k < 3 ? c_t[k + 1].x : 0.f) : c_t[k].x;
            const float rci = __shfl_sync(0xffffffffu, xr_i, laneR);
            const float rct = __shfl_sync(0xffffffffu, xr_t, laneR);

            float gv, gh, a, b;

            gv = n_i[k].x - u_i[k].x; gh = c_i[k].y - lci;
            a  = fsqrt_ap(fmaf(gv, gv, fmaf(gh, gh, EPS)));
            gv = n_t[k].x - u_t[k].x; gh = c_t[k].y - lct;
            b  = fsqrt_ap(fmaf(gv, gv, fmaf(gh, gh, EPS)));
            sum0 += fabsf(a - b);

            gv = n_i[k].y - u_i[k].y; gh = c_i[k].z - c_i[k].x;
            a  = fsqrt_ap(fmaf(gv, gv, fmaf(gh, gh, EPS)));
            gv = n_t[k].y - u_t[k].y; gh = c_t[k].z - c_t[k].x;
            b  = fsqrt_ap(fmaf(gv, gv, fmaf(gh, gh, EPS)));
            sum1 += fabsf(a - b);

            gv = n_i[k].z - u_i[k].z; gh = c_i[k].w - c_i[k].y;
            a  = fsqrt_ap(fmaf(gv, gv, fmaf(gh, gh, EPS)));
            gv = n_t[k].z - u_t[k].z; gh = c_t[k].w - c_t[k].y;
            b  = fsqrt_ap(fmaf(gv, gv, fmaf(gh, gh, EPS)));
            sum2 += fabsf(a - b);

            gv = n_i[k].w - u_i[k].w; gh = rci - c_i[k].z;
            a  = fsqrt_ap(fmaf(gv, gv, fmaf(gh, gh, EPS)));
            gv = n_t[k].w - u_t[k].w; gh = rct - c_t[k].z;
            b  = fsqrt_ap(fmaf(gv, gv, fmaf(gh, gh, EPS)));
            sum3 += fabsf(a - b);
        }

        // plane-last row zeroed n, but next iteration needs c = real row rg+1:
        // rare uniform reload (once per 512 rows; L1/L2 hit)
        if (r == HH - 1 && rg + 1 < total_rows) {
            #pragma unroll
            for (int k = 0; k < 4; ++k) {
                n_i[k] = ld4(pi + WW + k * 128);
                n_t[k] = ld4(pt + WW + k * 128);
            }
        }

        pi += WW; pt += WW; pfp += WW;
    };

    int rg = ws;
    for (; rg + 3 <= we; rg += 3) {
        step(Xi, Yi, Zi, Xt, Yt, Zt, rg);
        step(Yi, Zi, Xi, Yt, Zt, Xt, rg + 1);
        step(Zi, Xi, Yi, Zt, Xt, Yt, rg + 2);
    }
    if (rg < we) { step(Xi, Yi, Zi, Xt, Yt, Zt, rg); ++rg; }
    if (rg < we) { step(Yi, Zi, Xi, Yt, Zt, Xt, rg); ++rg; }

    float sum = (sum0 + sum1) + (sum2 + sum3);

    // ---------- block reduction + last-block-ticket finisher ----------
    #pragma unroll
    for (int o = 16; o > 0; o >>= 1)
        sum += __shfl_down_sync(0xffffffffu, sum, o);

    __shared__ float wsum[TPB / 32];
    __shared__ bool is_last;
    if (lane == 0) wsum[wid] = sum;
    __syncthreads();

    if (t == 0) {
        float s = wsum[0] + wsum[1] + wsum[2] + wsum[3];
        g_partials[blockIdx.x] = s;
        __threadfence();                               // partial visible before ticket
        unsigned done = atomicAdd(&g_ticket, 1u);
        is_last = (done == (unsigned)(NBLK - 1));
    }
    __syncthreads();

    if (is_last) {
        const volatile float* vp = (const volatile float*)g_partials;
        float s = 0.f;
        for (int i = t; i < NBLK; i += TPB)
            s += vp[i];

        #pragma unroll
        for (int o = 16; o > 0; o >>= 1)
            s += __shfl_down_sync(0xffffffffu, s, o);

        if (lane == 0) wsum[wid] = s;
        __syncthreads();
        if (t == 0) {
            out[0] = (wsum[0] + wsum[1] + wsum[2] + wsum[3]) * inv_n;
            g_ticket = 0;                              // reset for next graph replay
        }
    }
}

extern "C" void kernel_launch(void* const* d_in, const int* in_sizes, int n_in,
                              void* d_out, int out_size) {
    const float* in = (const float*)d_in[0];
    const float* tg = (const float*)d_in[1];
    float* out = (float*)d_out;

    const int total = in_sizes[0];                 // 32*3*512*512
    const int total_rows = total / WW;             // 49152

    grad_loss_kernel<<<NBLK, TPB>>>(in, tg, out, total_rows, 1.0f / (float)total);
}